// round 12
// baseline (speedup 1.0000x reference)
#include <cuda_runtime.h>
#include <cuda_fp16.h>
#include <math.h>
#include <stdint.h>

// ---------------- problem constants ----------------
#define DIMN   1024
#define SEQ    2048
#define BATCH  2
#define TOK    (BATCH*SEQ)    // 4096 tokens
#define HEADS  16
#define HD     64
#define MLPD   4096
#define DEPTH  6
#define ASCALE 0.03125f       // DIM^-0.5 (reference uses full dim)

#define FLAG_RESID 1
#define FLAG_GELU  2
#define FLAG_PACK  4

// SW128 swizzle (Swizzle<3,4,3>) on byte offsets within a 128B-row tile
#define SWZ(o) ((o) ^ (((o) >> 3) & 0x70))

// ---------------- scratch (device globals; no cudaMalloc allowed) ----------------
// fp16 hi/lo activations (tile = 128 rows x 64 k, SW128, 8192 elems = 16KB)
__device__ __half g_y_hi [(size_t)TOK * DIMN];
__device__ __half g_y_lo [(size_t)TOK * DIMN];
__device__ __half g_qp_hi[(size_t)TOK * 3 * DIMN];   // packed QKV
__device__ __half g_qp_lo[(size_t)TOK * 3 * DIMN];   // lo only written for Q cols
__device__ __half g_at_hi[(size_t)TOK * DIMN];
__device__ __half g_at_lo[(size_t)TOK * DIMN];
__device__ __half g_u_hi [(size_t)TOK * MLPD];
__device__ __half g_u_lo [(size_t)TOK * MLPD];
// weights: single fp16 (pre-transposed [N,K] K-major, pre-swizzled tiles)
__device__ __half g_wqkv[(size_t)DEPTH * DIMN * 3 * DIMN];
__device__ __half g_wo  [(size_t)DEPTH * DIMN * DIMN];
__device__ __half g_w1  [(size_t)DEPTH * DIMN * MLPD];
__device__ __half g_w2  [(size_t)DEPTH * MLPD * DIMN];

// ---------------- helpers ----------------
__device__ __forceinline__ uint32_t smem_u32(const void* p) {
    uint32_t a;
    asm("{ .reg .u64 t; cvta.to.shared.u64 t, %1; cvt.u32.u64 %0, t; }"
        : "=r"(a) : "l"(p));
    return a;
}
__device__ __forceinline__ void cpasync16(uint32_t s, const void* g) {
    asm volatile("cp.async.cg.shared.global [%0], [%1], 16;" :: "r"(s), "l"(g));
}
#define CP_COMMIT() asm volatile("cp.async.commit_group;" ::: "memory")
#define CP_WAIT(n)  asm volatile("cp.async.wait_group %0;" :: "n"(n) : "memory")

#define LDM_X4(r, a)                                                          \
    asm volatile("ldmatrix.sync.aligned.m8n8.x4.shared.b16 {%0,%1,%2,%3}, [%4];" \
                 : "=r"((r)[0]), "=r"((r)[1]), "=r"((r)[2]), "=r"((r)[3])     \
                 : "r"(a))
#define LDM_X4T(r, a)                                                         \
    asm volatile("ldmatrix.sync.aligned.m8n8.x4.trans.shared.b16 {%0,%1,%2,%3}, [%4];" \
                 : "=r"((r)[0]), "=r"((r)[1]), "=r"((r)[2]), "=r"((r)[3])     \
                 : "r"(a))

__device__ __forceinline__ void mma_h(float* c, const uint32_t* a,
                                      uint32_t b0, uint32_t b1) {
    asm volatile(
        "mma.sync.aligned.m16n8k16.row.col.f32.f16.f16.f32 "
        "{%0,%1,%2,%3}, {%4,%5,%6,%7}, {%8,%9}, {%0,%1,%2,%3};"
        : "+f"(c[0]), "+f"(c[1]), "+f"(c[2]), "+f"(c[3])
        : "r"(a[0]), "r"(a[1]), "r"(a[2]), "r"(a[3]), "r"(b0), "r"(b1));
}

__device__ __forceinline__ float gelu_exact(float x) {
    return 0.5f * x * (1.0f + erff(x * 0.70710678118654752f));
}
// pack two floats -> fp16 hi pair / fp16 lo pair
__device__ __forceinline__ void pack2h(float a, float b, uint32_t& h, uint32_t& l) {
    const __half ha = __float2half_rn(a);
    const __half hb = __float2half_rn(b);
    const __half la = __float2half_rn(a - __half2float(ha));
    const __half lb = __float2half_rn(b - __half2float(hb));
    h = (uint32_t)__half_as_ushort(ha) | ((uint32_t)__half_as_ushort(hb) << 16);
    l = (uint32_t)__half_as_ushort(la) | ((uint32_t)__half_as_ushort(lb) << 16);
}

// ---------------- layernorm -> packed fp16 hi/lo tiles ----------------
__global__ __launch_bounds__(256) void ln_pack(
    const float* __restrict__ x, const float* __restrict__ g,
    const float* __restrict__ b, __half* __restrict__ hi,
    __half* __restrict__ lo)
{
    __shared__ float redS[8], redQ[8];
    const int row = blockIdx.x;
    const int tid = threadIdx.x;
    const float4 v = reinterpret_cast<const float4*>(x)[(size_t)row * 256 + tid];
    float s = v.x + v.y + v.z + v.w;
    float q = v.x*v.x + v.y*v.y + v.z*v.z + v.w*v.w;
    #pragma unroll
    for (int off = 16; off; off >>= 1) {
        s += __shfl_xor_sync(0xffffffffu, s, off);
        q += __shfl_xor_sync(0xffffffffu, q, off);
    }
    if ((tid & 31) == 0) { redS[tid >> 5] = s; redQ[tid >> 5] = q; }
    __syncthreads();
    s = 0.f; q = 0.f;
    #pragma unroll
    for (int w = 0; w < 8; w++) { s += redS[w]; q += redQ[w]; }
    const float mean = s * (1.0f / DIMN);
    const float var  = q * (1.0f / DIMN) - mean * mean;
    const float rstd = rsqrtf(var + 1e-5f);
    const float4 gg = reinterpret_cast<const float4*>(g)[tid];
    const float4 bb = reinterpret_cast<const float4*>(b)[tid];
    const float o0 = (v.x - mean) * rstd * gg.x + bb.x;
    const float o1 = (v.y - mean) * rstd * gg.y + bb.y;
    const float o2 = (v.z - mean) * rstd * gg.z + bb.z;
    const float o3 = (v.w - mean) * rstd * gg.w + bb.w;
    uint32_t h0, l0, h1, l1;
    pack2h(o0, o1, h0, l0);
    pack2h(o2, o3, h1, l1);
    const int k = tid << 2;
    const size_t tile = (size_t)(row >> 7) * (DIMN / 64) + (k >> 6);
    const uint32_t off = SWZ((uint32_t)((row & 127) * 128 + ((k & 63) << 1)));
    *reinterpret_cast<uint2*>((char*)hi + tile * 16384 + off) = make_uint2(h0, h1);
    *reinterpret_cast<uint2*>((char*)lo + tile * 16384 + off) = make_uint2(l0, l1);
}

// ---------------- weight prep: fp32 W[K,N] -> fp16 [N,K] swizzled tiles ------
__global__ __launch_bounds__(256) void prep_kernel(
    const float* __restrict__ W, __half* __restrict__ hi, int K, int N)
{
    __shared__ __half shH[8192];
    const int nt = blockIdx.x, kc = blockIdx.y, layer = blockIdx.z;
    const float* Wp = W + (size_t)layer * K * N;
    const int tid = threadIdx.x;
    #pragma unroll
    for (int i = 0; i < 8; i++) {
        const int idx = tid + (i << 8);
        const int r  = idx >> 5;               // k_local 0..63
        const int c4 = (idx & 31) << 2;        // n_local 0..124
        const float4 v = *reinterpret_cast<const float4*>(
            Wp + (size_t)(kc * 64 + r) * N + nt * 128 + c4);
        const float f[4] = {v.x, v.y, v.z, v.w};
        #pragma unroll
        for (int j = 0; j < 4; j++) {
            const uint32_t sw = SWZ((uint32_t)((c4 + j) * 128 + r * 2));
            shH[sw >> 1] = __float2half_rn(f[j]);
        }
    }
    __syncthreads();
    const size_t tb = ((size_t)layer * gridDim.x * gridDim.y +
                       (size_t)nt * gridDim.y + kc) * 8192;
    uint4* dH = reinterpret_cast<uint4*>(hi + tb);
    const uint4* sH = reinterpret_cast<const uint4*>(shH);
    #pragma unroll
    for (int i = 0; i < 4; i++) {
        const int idx = tid + (i << 8);
        dH[idx] = sH[idx];
    }
}

// ---------------- mma.sync fp16 2-term GEMM ----------------
// C[M,N] = A@W (+bias)(+gelu)(+resid | ->pack). 128x128 CTA tile, K-chunk 64,
// 4-stage cp.async pipeline, 8 warps each 32(m)x64(n).
// Terms: Ahi*W + Alo*W   (W single fp16)
#define STAGES 4
#define STG_BYTES 49152          // Ahi 16K | Alo 16K | B 16K
#define GEMM_SMEM (STAGES * STG_BYTES)

__global__ __launch_bounds__(256, 1) void gemm_mma(
    int M, int N, int K,
    const __half* __restrict__ Ahi, const __half* __restrict__ Alo,
    const __half* __restrict__ B,
    float* __restrict__ C, const float* __restrict__ bias,
    __half* __restrict__ Phi, __half* __restrict__ Plo,
    int packNC, int loCols, int flags)
{
    extern __shared__ __align__(1024) char smem[];
    const uint32_t sb = smem_u32(smem);
    const int tid = threadIdx.x;
    const int wid = tid >> 5, lane = tid & 31;
    const int NC = K >> 6;
    const int bm = blockIdx.y << 7, bn = blockIdx.x << 7;
    const size_t at0 = (size_t)blockIdx.y * NC;
    const size_t bt0 = (size_t)blockIdx.x * NC;

    // ---- prologue: fill 3 of 4 stages ----
    #pragma unroll
    for (int s = 0; s < STAGES - 1; s++) {
        const char* ga_h = (const char*)Ahi + (at0 + s) * 16384;
        const char* ga_l = (const char*)Alo + (at0 + s) * 16384;
        const char* gb   = (const char*)B   + (bt0 + s) * 16384;
        const uint32_t ds = sb + s * STG_BYTES;
        #pragma unroll
        for (int i = 0; i < 4; i++) {
            const int idx = (tid + (i << 8)) << 4;
            cpasync16(ds +     0 + idx, ga_h + idx);
            cpasync16(ds + 16384 + idx, ga_l + idx);
            cpasync16(ds + 32768 + idx, gb   + idx);
        }
        CP_COMMIT();
    }

    float acc[2][8][4];
    #pragma unroll
    for (int i = 0; i < 2; i++)
        #pragma unroll
        for (int j = 0; j < 8; j++)
            #pragma unroll
            for (int u = 0; u < 4; u++) acc[i][j][u] = 0.f;

    const int wm0 = (wid & 3) << 5;
    const int wn0 = (wid >> 2) << 6;
    uint32_t aoff[2], boff[4];
    #pragma unroll
    for (int mt = 0; mt < 2; mt++)
        aoff[mt] = (uint32_t)((wm0 + (mt << 4) + (lane & 15)) * 128 + ((lane >> 4) << 4));
    #pragma unroll
    for (int g = 0; g < 4; g++)
        boff[g] = (uint32_t)((wn0 + (g << 4) + (lane & 7) + ((lane >> 1) & 8)) * 128 +
                             ((lane & 8) << 1));

    for (int c = 0; c < NC; c++) {
        CP_WAIT(2);
        __syncthreads();

        const int cn = c + STAGES - 1;
        if (cn < NC) {
            const char* ga_h = (const char*)Ahi + (at0 + cn) * 16384;
            const char* ga_l = (const char*)Alo + (at0 + cn) * 16384;
            const char* gb   = (const char*)B   + (bt0 + cn) * 16384;
            const uint32_t ds = sb + (uint32_t)(cn & 3) * STG_BYTES;
            #pragma unroll
            for (int i = 0; i < 4; i++) {
                const int idx = (tid + (i << 8)) << 4;
                cpasync16(ds +     0 + idx, ga_h + idx);
                cpasync16(ds + 16384 + idx, ga_l + idx);
                cpasync16(ds + 32768 + idx, gb   + idx);
            }
        }
        CP_COMMIT();   // unconditional to keep group accounting uniform

        const uint32_t stb = sb + (uint32_t)(c & 3) * STG_BYTES;
        #pragma unroll
        for (int ks = 0; ks < 4; ks++) {
            const uint32_t kb = (uint32_t)(ks << 5);
            uint32_t ah[2][4], al[2][4], bf4[4][4];
            #pragma unroll
            for (int g = 0; g < 4; g++)
                LDM_X4(bf4[g], stb + 32768 + SWZ(boff[g] + kb));
            #pragma unroll
            for (int mt = 0; mt < 2; mt++)
                LDM_X4(ah[mt], stb + SWZ(aoff[mt] + kb));
            #pragma unroll
            for (int mt = 0; mt < 2; mt++)
                #pragma unroll
                for (int g = 0; g < 4; g++) {
                    mma_h(acc[mt][2*g],   ah[mt], bf4[g][0], bf4[g][1]);
                    mma_h(acc[mt][2*g+1], ah[mt], bf4[g][2], bf4[g][3]);
                }
            #pragma unroll
            for (int mt = 0; mt < 2; mt++)
                LDM_X4(al[mt], stb + 16384 + SWZ(aoff[mt] + kb));
            #pragma unroll
            for (int mt = 0; mt < 2; mt++)
                #pragma unroll
                for (int g = 0; g < 4; g++) {
                    mma_h(acc[mt][2*g],   al[mt], bf4[g][0], bf4[g][1]);
                    mma_h(acc[mt][2*g+1], al[mt], bf4[g][2], bf4[g][3]);
                }
        }
    }

    // ---- epilogue ----
    #pragma unroll
    for (int mt = 0; mt < 2; mt++) {
        const int r0 = bm + wm0 + (mt << 4) + (lane >> 2);
        #pragma unroll
        for (int nt = 0; nt < 8; nt++) {
            const int col = bn + wn0 + (nt << 3) + ((lane & 3) << 1);
            float va0 = acc[mt][nt][0], va1 = acc[mt][nt][1];
            float vb0 = acc[mt][nt][2], vb1 = acc[mt][nt][3];
            if (bias) {
                const float2 bv = *reinterpret_cast<const float2*>(bias + col);
                va0 += bv.x; va1 += bv.y; vb0 += bv.x; vb1 += bv.y;
            }
            if (flags & FLAG_GELU) {
                va0 = gelu_exact(va0); va1 = gelu_exact(va1);
                vb0 = gelu_exact(vb0); vb1 = gelu_exact(vb1);
            }
            if (flags & FLAG_PACK) {
                #pragma unroll
                for (int rr = 0; rr < 2; rr++) {
                    const int r = r0 + (rr << 3);
                    const float pa = rr ? vb0 : va0;
                    const float pb = rr ? vb1 : va1;
                    uint32_t hv, lv;
                    pack2h(pa, pb, hv, lv);
                    const size_t tile = (size_t)(r >> 7) * packNC + (col >> 6);
                    const uint32_t off = SWZ((uint32_t)((r & 127) * 128 + ((col & 63) << 1)));
                    *reinterpret_cast<uint32_t*>((char*)Phi + tile * 16384 + off) = hv;
                    if (col < loCols)
                        *reinterpret_cast<uint32_t*>((char*)Plo + tile * 16384 + off) = lv;
                }
            } else {
                float* p0 = C + (size_t)r0 * N + col;
                float* p1 = C + (size_t)(r0 + 8) * N + col;
                if (flags & FLAG_RESID) {
                    const float2 c0 = *reinterpret_cast<const float2*>(p0);
                    const float2 c1 = *reinterpret_cast<const float2*>(p1);
                    va0 += c0.x; va1 += c0.y; vb0 += c1.x; vb1 += c1.y;
                }
                *reinterpret_cast<float2*>(p0) = make_float2(va0, va1);
                *reinterpret_cast<float2*>(p1) = make_float2(vb0, vb1);
            }
        }
    }
}

// ---------------- mma.sync flash attention, fp16 2-term, hd=64 ---------------
// CTA: 128 threads (4 warps), 64 q-rows, kv tiles of 64, 3-stage K/V pipeline.
// Q: hi+lo fp16; K,V: hi only. Output: packed hi/lo.
#define NSTG 3
#define ATT_SMEM (16384 + NSTG * 16384)   // Q(hi+lo) + stages of (Kh 8K | Vh 8K)
#define PSC 1024.0f                        // P pre-scale (keeps p-lo out of subnormals)

__global__ __launch_bounds__(128, 3) void attn_mma(
    const __half* __restrict__ qkvh, const __half* __restrict__ qkvl,
    __half* __restrict__ ohi, __half* __restrict__ olo)
{
    extern __shared__ __align__(1024) char asmem[];
    const uint32_t sb = smem_u32(asmem);
    const int tid = threadIdx.x;
    const int wid = tid >> 5, lane = tid & 31;
    const int bh = blockIdx.y;
    const int bb = bh >> 4, h = bh & 15;
    const int q0 = blockIdx.x << 6;
    const int grow0 = bb * SEQ + q0;
    const int hq = h;
    const int hk = (DIMN >> 6) + h;
    const int hv = (2 * DIMN >> 6) + h;

    auto src64 = [&](const __half* base, int coltile, int grows) -> const char* {
        return (const char*)base + ((size_t)(grows >> 7) * 48 + coltile) * 16384
               + (size_t)(grows & 127) * 128;
    };
    auto issue_stage = [&](int it) {
        const int gkv = bb * SEQ + (it << 6);
        const char* kh_ = src64(qkvh, hk, gkv);
        const char* vh_ = src64(qkvh, hv, gkv);
        const uint32_t ds = sb + 16384 + (uint32_t)(it % NSTG) * 16384;
        #pragma unroll
        for (int i = 0; i < 4; i++) {
            const int idx = (tid + (i << 7)) << 4;
            cpasync16(ds +        idx, kh_ + idx);
            cpasync16(ds + 8192 + idx, vh_ + idx);
        }
    };

    // ---- prologue: group0 = Q(hi+lo) + stage0; group1 = stage1 ----
    {
        const char* qh_ = src64(qkvh, hq, grow0);
        const char* ql_ = src64(qkvl, hq, grow0);
        #pragma unroll
        for (int i = 0; i < 4; i++) {
            const int idx = (tid + (i << 7)) << 4;
            cpasync16(sb +        idx, qh_ + idx);
            cpasync16(sb + 8192 + idx, ql_ + idx);
        }
        issue_stage(0);
        CP_COMMIT();
        issue_stage(1);
        CP_COMMIT();
    }
    CP_WAIT(1);
    __syncthreads();

    // ---- preload Q fragments ----
    const uint32_t aoff = (uint32_t)(((wid << 4) + (lane & 15)) * 128 + ((lane >> 4) << 4));
    uint32_t qhf[4][4], qlf[4][4];
    #pragma unroll
    for (int kb = 0; kb < 4; kb++) {
        LDM_X4(qhf[kb], sb +        SWZ(aoff + (kb << 5)));
        LDM_X4(qlf[kb], sb + 8192 + SWZ(aoff + (kb << 5)));
    }

    uint32_t boffK[4], voffV[4];
    #pragma unroll
    for (int g = 0; g < 4; g++) {
        boffK[g] = (uint32_t)(((g << 4) + (lane & 7) + ((lane >> 1) & 8)) * 128 +
                              ((lane & 8) << 1));
        voffV[g] = (uint32_t)((lane & 15) * 128 + ((lane >> 4) << 4) + (g << 5));
    }

    float oacc[8][4];
    #pragma unroll
    for (int j = 0; j < 8; j++)
        #pragma unroll
        for (int u = 0; u < 4; u++) oacc[j][u] = 0.f;
    float m0 = -1e30f, m1 = -1e30f, l0 = 0.f, l1 = 0.f;

    const int NIT = SEQ / 64;
    for (int it = 0; it < NIT; it++) {
        CP_WAIT(1);
        __syncthreads();
        if (it + 2 < NIT) issue_stage(it + 2);
        CP_COMMIT();

        const uint32_t kbuf = sb + 16384 + (uint32_t)(it % NSTG) * 16384;
        const uint32_t vbuf = kbuf + 8192;

        // ---- S = Q K^T (2-term: qh*kh + ql*kh) ----
        float sacc[8][4];
        #pragma unroll
        for (int j = 0; j < 8; j++)
            #pragma unroll
            for (int u = 0; u < 4; u++) sacc[j][u] = 0.f;

        #pragma unroll
        for (int kb = 0; kb < 4; kb++) {
            const uint32_t kbb = (uint32_t)(kb << 5);
            uint32_t bh4[4][4];
            #pragma unroll
            for (int g = 0; g < 4; g++)
                LDM_X4(bh4[g], kbuf + SWZ(boffK[g] + kbb));
            #pragma unroll
            for (int g = 0; g < 4; g++) {
                mma_h(sacc[2*g],   qhf[kb], bh4[g][0], bh4[g][1]);
                mma_h(sacc[2*g+1], qhf[kb], bh4[g][2], bh4[g][3]);
                mma_h(sacc[2*g],   qlf[kb], bh4[g][0], bh4[g][1]);
                mma_h(sacc[2*g+1], qlf[kb], bh4[g][2], bh4[g][3]);
            }
        }

        // ---- online softmax ----
        #pragma unroll
        for (int j = 0; j < 8; j++)
            #pragma unroll
            for (int u = 0; u < 4; u++) sacc[j][u] *= ASCALE;

        float mx0 = -1e30f, mx1 = -1e30f;
        #pragma unroll
        for (int j = 0; j < 8; j++) {
            mx0 = fmaxf(mx0, fmaxf(sacc[j][0], sacc[j][1]));
            mx1 = fmaxf(mx1, fmaxf(sacc[j][2], sacc[j][3]));
        }
        mx0 = fmaxf(mx0, __shfl_xor_sync(0xffffffffu, mx0, 1));
        mx0 = fmaxf(mx0, __shfl_xor_sync(0xffffffffu, mx0, 2));
        mx1 = fmaxf(mx1, __shfl_xor_sync(0xffffffffu, mx1, 1));
        mx1 = fmaxf(mx1, __shfl_xor_sync(0xffffffffu, mx1, 2));
        const float nm0 = fmaxf(m0, mx0), nm1 = fmaxf(m1, mx1);
        const float al0 = __expf(m0 - nm0), al1 = __expf(m1 - nm1);
        m0 = nm0; m1 = nm1;
        float rs0 = 0.f, rs1 = 0.f;
        #pragma unroll
        for (int j = 0; j < 8; j++) {
            sacc[j][0] = __expf(sacc[j][0] - m0); rs0 += sacc[j][0];
            sacc[j][1] = __expf(sacc[j][1] - m0); rs0 += sacc[j][1];
            sacc[j][2] = __expf(sacc[j][2] - m1); rs1 += sacc[j][2];
            sacc[j][3] = __expf(sacc[j][3] - m1); rs1 += sacc[j][3];
        }
        l0 = l0 * al0 + rs0;
        l1 = l1 * al1 + rs1;
        #pragma unroll
        for (int j = 0; j < 8; j++) {
            oacc[j][0] *= al0; oacc[j][1] *= al0;
            oacc[j][2] *= al1; oacc[j][3] *= al1;
        }

        // ---- O += P V (2-term: ph*vh + pl*vh; P pre-scaled by PSC) ----
        #pragma unroll
        for (int jp = 0; jp < 4; jp++) {
            uint32_t pah[4], pal[4];
            pack2h(sacc[2*jp][0]   * PSC, sacc[2*jp][1]   * PSC, pah[0], pal[0]);
            pack2h(sacc[2*jp][2]   * PSC, sacc[2*jp][3]   * PSC, pah[1], pal[1]);
            pack2h(sacc[2*jp+1][0] * PSC, sacc[2*jp+1][1] * PSC, pah[2], pal[2]);
            pack2h(sacc[2*jp+1][2] * PSC, sacc[2*jp+1][3] * PSC, pah[3], pal[3]);
            const uint32_t rowb = (uint32_t)(jp << 11);
            #pragma unroll
            for (int g = 0; g < 4; g++) {
                uint32_t vh4[4];
                LDM_X4T(vh4, vbuf + SWZ(voffV[g] + rowb));
                mma_h(oacc[2*g],   pah, vh4[0], vh4[1]);
                mma_h(oacc[2*g+1], pah, vh4[2], vh4[3]);
                mma_h(oacc[2*g],   pal, vh4[0], vh4[1]);
                mma_h(oacc[2*g+1], pal, vh4[2], vh4[3]);
            }
        }
    }

    // ---- finalize & write packed hi/lo ----
    l0 += __shfl_xor_sync(0xffffffffu, l0, 1);
    l0 += __shfl_xor_sync(0xffffffffu, l0, 2);
    l1 += __shfl_xor_sync(0xffffffffu, l1, 1);
    l1 += __shfl_xor_sync(0xffffffffu, l1, 2);
    const float il0 = 1.0f / (l0 * PSC), il1 = 1.0f / (l1 * PSC);

    const int r0g = grow0 + (wid << 4) + (lane >> 2);
    #pragma unroll
    for (int j = 0; j < 8; j++) {
        const int k0 = h * HD + (j << 3) + ((lane & 3) << 1);
        uint32_t hv0, lv0, hv1, lv1;
        pack2h(oacc[j][0] * il0, oacc[j][1] * il0, hv0, lv0);
        pack2h(oacc[j][2] * il1, oacc[j][3] * il1, hv1, lv1);
        const size_t t0 = (size_t)(r0g >> 7) * 16 + (k0 >> 6);
        const uint32_t of0 = SWZ((uint32_t)((r0g & 127) * 128 + ((k0 & 63) << 1)));
        *reinterpret_cast<uint32_t*>((char*)ohi + t0 * 16384 + of0) = hv0;
        *reinterpret_cast<uint32_t*>((char*)olo + t0 * 16384 + of0) = lv0;
        const int r1g = r0g + 8;
        const size_t t1 = (size_t)(r1g >> 7) * 16 + (k0 >> 6);
        const uint32_t of1 = SWZ((uint32_t)((r1g & 127) * 128 + ((k0 & 63) << 1)));
        *reinterpret_cast<uint32_t*>((char*)ohi + t1 * 16384 + of1) = hv1;
        *reinterpret_cast<uint32_t*>((char*)olo + t1 * 16384 + of1) = lv1;
    }
}

// ---------------- launch ----------------
extern "C" void kernel_launch(void* const* d_in, const int* in_sizes, int n_in,
                              void* d_out, int out_size)
{
    const float* x    = (const float*)d_in[0];
    const float* Wqkv = (const float*)d_in[1];
    const float* Wout = (const float*)d_in[2];
    const float* bout = (const float*)d_in[3];
    const float* ln1g = (const float*)d_in[4];
    const float* ln1b = (const float*)d_in[5];
    const float* ln2g = (const float*)d_in[6];
    const float* ln2b = (const float*)d_in[7];
    const float* W1   = (const float*)d_in[8];
    const float* b1   = (const float*)d_in[9];
    const float* W2   = (const float*)d_in[10];
    const float* b2   = (const float*)d_in[11];
    float* h = (float*)d_out;

    __half *yh, *yl, *qph, *qpl, *ath, *atl, *uh, *ul;
    cudaGetSymbolAddress((void**)&yh,  g_y_hi);
    cudaGetSymbolAddress((void**)&yl,  g_y_lo);
    cudaGetSymbolAddress((void**)&qph, g_qp_hi);
    cudaGetSymbolAddress((void**)&qpl, g_qp_lo);
    cudaGetSymbolAddress((void**)&ath, g_at_hi);
    cudaGetSymbolAddress((void**)&atl, g_at_lo);
    cudaGetSymbolAddress((void**)&uh,  g_u_hi);
    cudaGetSymbolAddress((void**)&ul,  g_u_lo);
    __half *wq, *wo, *w1p, *w2p;
    cudaGetSymbolAddress((void**)&wq,  g_wqkv);
    cudaGetSymbolAddress((void**)&wo,  g_wo);
    cudaGetSymbolAddress((void**)&w1p, g_w1);
    cudaGetSymbolAddress((void**)&w2p, g_w2);

    cudaFuncSetAttribute(gemm_mma, cudaFuncAttributeMaxDynamicSharedMemorySize, GEMM_SMEM);
    cudaFuncSetAttribute(attn_mma, cudaFuncAttributeMaxDynamicSharedMemorySize, ATT_SMEM);

    prep_kernel<<<dim3(3 * DIMN / 128, DIMN / 64, DEPTH), 256>>>(Wqkv, wq, DIMN, 3 * DIMN);
    prep_kernel<<<dim3(DIMN / 128,     DIMN / 64, DEPTH), 256>>>(Wout, wo, DIMN, DIMN);
    prep_kernel<<<dim3(MLPD / 128,     DIMN / 64, DEPTH), 256>>>(W1,   w1p, DIMN, MLPD);
    prep_kernel<<<dim3(DIMN / 128,     MLPD / 64, DEPTH), 256>>>(W2,   w2p, MLPD, DIMN);

    cudaMemcpyAsync(h, x, (size_t)TOK * DIMN * sizeof(float), cudaMemcpyDeviceToDevice);

    for (int l = 0; l < DEPTH; l++) {
        const size_t woffQ = (size_t)l * DIMN * 3 * DIMN;
        const size_t woffO = (size_t)l * DIMN * DIMN;
        const size_t woff1 = (size_t)l * DIMN * MLPD;
        const size_t woff2 = (size_t)l * MLPD * DIMN;
        const float* bo  = bout + (size_t)l * DIMN;
        const float* g1  = ln1g + (size_t)l * DIMN;
        const float* bb1 = ln1b + (size_t)l * DIMN;
        const float* g2  = ln2g + (size_t)l * DIMN;
        const float* bb2 = ln2b + (size_t)l * DIMN;
        const float* bf1 = b1   + (size_t)l * MLPD;
        const float* bf2 = b2   + (size_t)l * DIMN;

        ln_pack<<<TOK, 256>>>(h, g1, bb1, yh, yl);
        gemm_mma<<<dim3(3 * DIMN / 128, TOK / 128), 256, GEMM_SMEM>>>(
            TOK, 3 * DIMN, DIMN, yh, yl, wq + woffQ,
            nullptr, nullptr, qph, qpl, 3 * DIMN / 64, DIMN, FLAG_PACK);
        attn_mma<<<dim3(SEQ / 64, BATCH * HEADS), 128, ATT_SMEM>>>(qph, qpl, ath, atl);
        gemm_mma<<<dim3(DIMN / 128, TOK / 128), 256, GEMM_SMEM>>>(
            TOK, DIMN, DIMN, ath, atl, wo + woffO,
            h, bo, nullptr, nullptr, 0, 0, FLAG_RESID);
        ln_pack<<<TOK, 256>>>(h, g2, bb2, yh, yl);
        gemm_mma<<<dim3(MLPD / 128, TOK / 128), 256, GEMM_SMEM>>>(
            TOK, MLPD, DIMN, yh, yl, w1p + woff1,
            nullptr, bf1, uh, ul, MLPD / 64, MLPD, FLAG_GELU | FLAG_PACK);
        gemm_mma<<<dim3(DIMN / 128, TOK / 128), 256, GEMM_SMEM>>>(
            TOK, DIMN, MLPD, uh, ul, w2p + woff2,
            h, bf2, nullptr, nullptr, 0, 0, FLAG_RESID);
    }
}

// round 13
// speedup vs baseline: 1.5217x; 1.5217x over previous
#include <cuda_runtime.h>
#include <cuda_bf16.h>
#include <math.h>
#include <stdint.h>

// ---------------- problem constants ----------------
#define DIMN   1024
#define SEQ    2048
#define BATCH  2
#define TOK    (BATCH*SEQ)    // 4096 tokens
#define HEADS  16
#define HD     64
#define MLPD   4096
#define DEPTH  6
#define ASCALE 0.03125f       // DIM^-0.5 (reference uses full dim)

#define FLAG_RESID 1
#define FLAG_GELU  2
#define FLAG_PACK  4

// SW128 swizzle (Swizzle<3,4,3>) on byte offsets within a 128B-row tile
#define SWZ(o) ((o) ^ (((o) >> 3) & 0x70))

// ---------------- scratch (device globals; no cudaMalloc allowed) ----------------
// packed bf16 activations (tile = 128 rows x 64 k, SW128, 8192 elems = 16KB)
__device__ __nv_bfloat16 g_y_hi [(size_t)TOK * DIMN];
__device__ __nv_bfloat16 g_y_lo [(size_t)TOK * DIMN];
__device__ __nv_bfloat16 g_qp_hi[(size_t)TOK * 3 * DIMN];   // packed QKV (hi only)
__device__ __nv_bfloat16 g_at_hi[(size_t)TOK * DIMN];       // attn out (hi only)
__device__ __nv_bfloat16 g_u_hi [(size_t)TOK * MLPD];
__device__ __nv_bfloat16 g_u_lo [(size_t)TOK * MLPD];
// weights (pre-transposed [N,K] K-major, pre-swizzled tiles)
__device__ __nv_bfloat16 g_wq_hi[(size_t)DEPTH * DIMN * 3 * DIMN];   // hi only
__device__ __nv_bfloat16 g_wo_hi[(size_t)DEPTH * DIMN * DIMN];       // hi only
__device__ __nv_bfloat16 g_w1_hi[(size_t)DEPTH * DIMN * MLPD];
__device__ __nv_bfloat16 g_w1_lo[(size_t)DEPTH * DIMN * MLPD];
__device__ __nv_bfloat16 g_w2_hi[(size_t)DEPTH * MLPD * DIMN];
__device__ __nv_bfloat16 g_w2_lo[(size_t)DEPTH * MLPD * DIMN];

// ---------------- helpers ----------------
__device__ __forceinline__ uint32_t smem_u32(const void* p) {
    uint32_t a;
    asm("{ .reg .u64 t; cvta.to.shared.u64 t, %1; cvt.u32.u64 %0, t; }"
        : "=r"(a) : "l"(p));
    return a;
}
__device__ __forceinline__ void cpasync16(uint32_t s, const void* g) {
    asm volatile("cp.async.cg.shared.global [%0], [%1], 16;" :: "r"(s), "l"(g));
}
#define CP_COMMIT() asm volatile("cp.async.commit_group;" ::: "memory")
#define CP_WAIT(n)  asm volatile("cp.async.wait_group %0;" :: "n"(n) : "memory")

#define LDM_X4(r, a)                                                          \
    asm volatile("ldmatrix.sync.aligned.m8n8.x4.shared.b16 {%0,%1,%2,%3}, [%4];" \
                 : "=r"((r)[0]), "=r"((r)[1]), "=r"((r)[2]), "=r"((r)[3])     \
                 : "r"(a))
#define LDM_X4T(r, a)                                                         \
    asm volatile("ldmatrix.sync.aligned.m8n8.x4.trans.shared.b16 {%0,%1,%2,%3}, [%4];" \
                 : "=r"((r)[0]), "=r"((r)[1]), "=r"((r)[2]), "=r"((r)[3])     \
                 : "r"(a))

__device__ __forceinline__ void mma_bf(float* c, const uint32_t* a,
                                       uint32_t b0, uint32_t b1) {
    asm volatile(
        "mma.sync.aligned.m16n8k16.row.col.f32.bf16.bf16.f32 "
        "{%0,%1,%2,%3}, {%4,%5,%6,%7}, {%8,%9}, {%0,%1,%2,%3};"
        : "+f"(c[0]), "+f"(c[1]), "+f"(c[2]), "+f"(c[3])
        : "r"(a[0]), "r"(a[1]), "r"(a[2]), "r"(a[3]), "r"(b0), "r"(b1));
}

__device__ __forceinline__ float gelu_exact(float x) {
    return 0.5f * x * (1.0f + erff(x * 0.70710678118654752f));
}
// pack two floats -> hi bf16 pair / lo bf16 pair
__device__ __forceinline__ void pack2(float a, float b, uint32_t& h, uint32_t& l) {
    const __nv_bfloat16 ha = __float2bfloat16(a);
    const __nv_bfloat16 hb = __float2bfloat16(b);
    const __nv_bfloat16 la = __float2bfloat16(a - __bfloat162float(ha));
    const __nv_bfloat16 lb = __float2bfloat16(b - __bfloat162float(hb));
    h = (uint32_t)__bfloat16_as_ushort(ha) | ((uint32_t)__bfloat16_as_ushort(hb) << 16);
    l = (uint32_t)__bfloat16_as_ushort(la) | ((uint32_t)__bfloat16_as_ushort(lb) << 16);
}
__device__ __forceinline__ uint32_t bfpair(float a, float b) {
    return (uint32_t)__bfloat16_as_ushort(__float2bfloat16(a)) |
           ((uint32_t)__bfloat16_as_ushort(__float2bfloat16(b)) << 16);
}

// ---------------- layernorm -> packed hi/lo tiles ----------------
__global__ __launch_bounds__(256) void ln_pack(
    const float* __restrict__ x, const float* __restrict__ g,
    const float* __restrict__ b, __nv_bfloat16* __restrict__ hi,
    __nv_bfloat16* __restrict__ lo)
{
    __shared__ float redS[8], redQ[8];
    const int row = blockIdx.x;
    const int tid = threadIdx.x;
    const float4 v = reinterpret_cast<const float4*>(x)[(size_t)row * 256 + tid];
    float s = v.x + v.y + v.z + v.w;
    float q = v.x*v.x + v.y*v.y + v.z*v.z + v.w*v.w;
    #pragma unroll
    for (int off = 16; off; off >>= 1) {
        s += __shfl_xor_sync(0xffffffffu, s, off);
        q += __shfl_xor_sync(0xffffffffu, q, off);
    }
    if ((tid & 31) == 0) { redS[tid >> 5] = s; redQ[tid >> 5] = q; }
    __syncthreads();
    s = 0.f; q = 0.f;
    #pragma unroll
    for (int w = 0; w < 8; w++) { s += redS[w]; q += redQ[w]; }
    const float mean = s * (1.0f / DIMN);
    const float var  = q * (1.0f / DIMN) - mean * mean;
    const float rstd = rsqrtf(var + 1e-5f);
    const float4 gg = reinterpret_cast<const float4*>(g)[tid];
    const float4 bb = reinterpret_cast<const float4*>(b)[tid];
    const float o0 = (v.x - mean) * rstd * gg.x + bb.x;
    const float o1 = (v.y - mean) * rstd * gg.y + bb.y;
    const float o2 = (v.z - mean) * rstd * gg.z + bb.z;
    const float o3 = (v.w - mean) * rstd * gg.w + bb.w;
    uint32_t h0, l0, h1, l1;
    pack2(o0, o1, h0, l0);
    pack2(o2, o3, h1, l1);
    const int k = tid << 2;
    const size_t tile = (size_t)(row >> 7) * (DIMN / 64) + (k >> 6);
    const uint32_t off = SWZ((uint32_t)((row & 127) * 128 + ((k & 63) << 1)));
    *reinterpret_cast<uint2*>((char*)hi + tile * 16384 + off) = make_uint2(h0, h1);
    *reinterpret_cast<uint2*>((char*)lo + tile * 16384 + off) = make_uint2(l0, l1);
}

// ---------------- weight prep: fp32 W[K,N] -> packed hi(/lo) bf16 tiles ------
// paired-k mapping: each thread packs two adjacent k for one n -> 4B smem stores
__global__ __launch_bounds__(256) void prep_kernel(
    const float* __restrict__ W, __nv_bfloat16* __restrict__ hi,
    __nv_bfloat16* __restrict__ lo, int K, int N)
{
    __shared__ uint32_t shH[4096], shL[4096];
    const int nt = blockIdx.x, kc = blockIdx.y, layer = blockIdx.z;
    const float* Wp = W + (size_t)layer * K * N;
    const int tid = threadIdx.x;
    const bool wlo = (lo != nullptr);
    #pragma unroll
    for (int i = 0; i < 16; i++) {
        const int idx = tid + (i << 8);        // 0..4095
        const int n  = idx & 127;              // n_local
        const int r2 = idx >> 7;               // k pair index 0..31
        const size_t gbase = (size_t)(kc * 64 + 2 * r2) * N + nt * 128 + n;
        const float f0 = Wp[gbase];
        const float f1 = Wp[gbase + N];
        uint32_t h, l;
        pack2(f0, f1, h, l);
        const uint32_t w = SWZ((uint32_t)(n * 128 + (r2 << 2))) >> 2;
        shH[w] = h;
        if (wlo) shL[w] = l;
    }
    __syncthreads();
    const size_t tb = ((size_t)layer * gridDim.x * gridDim.y +
                       (size_t)nt * gridDim.y + kc) * 8192;
    uint4* dH = reinterpret_cast<uint4*>(hi + tb);
    const uint4* sH = reinterpret_cast<const uint4*>(shH);
    #pragma unroll
    for (int i = 0; i < 4; i++) {
        const int idx = tid + (i << 8);
        dH[idx] = sH[idx];
    }
    if (wlo) {
        uint4* dL = reinterpret_cast<uint4*>(lo + tb);
        const uint4* sL = reinterpret_cast<const uint4*>(shL);
        #pragma unroll
        for (int i = 0; i < 4; i++) {
            const int idx = tid + (i << 8);
            dL[idx] = sL[idx];
        }
    }
}

// ---------------- mma.sync split-bf16 GEMM (TERMS = 1 or 3) ----------------
// C[M,N] = A@W (+bias)(+gelu)(+resid | ->pack). 128x128 CTA tile, K-chunk 64,
// 3-stage cp.async pipeline, 8 warps each 32(m)x64(n).
#define STAGES 3
#define STG_BYTES 65536          // Ahi 16K | Alo 16K | Bhi 16K | Blo 16K
#define GEMM_SMEM (STAGES * STG_BYTES)

template<int TERMS>
__global__ __launch_bounds__(256, 1) void gemm_mma(
    int M, int N, int K,
    const __nv_bfloat16* __restrict__ Ahi, const __nv_bfloat16* __restrict__ Alo,
    const __nv_bfloat16* __restrict__ Bhi, const __nv_bfloat16* __restrict__ Blo,
    float* __restrict__ C, const float* __restrict__ bias,
    __nv_bfloat16* __restrict__ Phi, __nv_bfloat16* __restrict__ Plo,
    int packNC, int loCols, int flags)
{
    extern __shared__ __align__(1024) char smem[];
    const uint32_t sb = smem_u32(smem);
    const int tid = threadIdx.x;
    const int wid = tid >> 5, lane = tid & 31;
    const int NC = K >> 6;
    const int bm = blockIdx.y << 7, bn = blockIdx.x << 7;
    const size_t at0 = (size_t)blockIdx.y * NC;
    const size_t bt0 = (size_t)blockIdx.x * NC;

    #pragma unroll
    for (int s = 0; s < STAGES; s++) {
        const char* ga_h = (const char*)Ahi + (at0 + s) * 16384;
        const char* gb_h = (const char*)Bhi + (bt0 + s) * 16384;
        const char* ga_l = (TERMS == 3) ? (const char*)Alo + (at0 + s) * 16384 : nullptr;
        const char* gb_l = (TERMS == 3) ? (const char*)Blo + (bt0 + s) * 16384 : nullptr;
        const uint32_t ds = sb + s * STG_BYTES;
        #pragma unroll
        for (int i = 0; i < 4; i++) {
            const int idx = (tid + (i << 8)) << 4;
            cpasync16(ds +     0 + idx, ga_h + idx);
            cpasync16(ds + 32768 + idx, gb_h + idx);
            if (TERMS == 3) {
                cpasync16(ds + 16384 + idx, ga_l + idx);
                cpasync16(ds + 49152 + idx, gb_l + idx);
            }
        }
        CP_COMMIT();
    }

    float acc[2][8][4];
    #pragma unroll
    for (int i = 0; i < 2; i++)
        #pragma unroll
        for (int j = 0; j < 8; j++)
            #pragma unroll
            for (int u = 0; u < 4; u++) acc[i][j][u] = 0.f;

    const int wm0 = (wid & 3) << 5;
    const int wn0 = (wid >> 2) << 6;
    uint32_t aoff[2], boff[4];
    #pragma unroll
    for (int mt = 0; mt < 2; mt++)
        aoff[mt] = (uint32_t)((wm0 + (mt << 4) + (lane & 15)) * 128 + ((lane >> 4) << 4));
    #pragma unroll
    for (int g = 0; g < 4; g++)
        boff[g] = (uint32_t)((wn0 + (g << 4) + (lane & 7) + ((lane >> 1) & 8)) * 128 +
                             ((lane & 8) << 1));

    for (int c = 0; c < NC; c++) {
        const int n_after = (c + STAGES <= NC ? STAGES : NC - c) - 1;
        if (n_after >= 2) CP_WAIT(2);
        else if (n_after == 1) CP_WAIT(1);
        else CP_WAIT(0);
        __syncthreads();

        const uint32_t stb = sb + (uint32_t)(c % STAGES) * STG_BYTES;
        #pragma unroll
        for (int ks = 0; ks < 4; ks++) {
            const uint32_t kb = (uint32_t)(ks << 5);
            uint32_t ah[2][4], bf4[4][4];
            #pragma unroll
            for (int mt = 0; mt < 2; mt++)
                LDM_X4(ah[mt], stb + SWZ(aoff[mt] + kb));
            #pragma unroll
            for (int g = 0; g < 4; g++)
                LDM_X4(bf4[g], stb + 32768 + SWZ(boff[g] + kb));
            #pragma unroll
            for (int mt = 0; mt < 2; mt++)
                #pragma unroll
                for (int g = 0; g < 4; g++) {
                    mma_bf(acc[mt][2*g],   ah[mt], bf4[g][0], bf4[g][1]);
                    mma_bf(acc[mt][2*g+1], ah[mt], bf4[g][2], bf4[g][3]);
                }
            if (TERMS == 3) {
                uint32_t al[2][4];
                #pragma unroll
                for (int mt = 0; mt < 2; mt++)
                    LDM_X4(al[mt], stb + 16384 + SWZ(aoff[mt] + kb));
                #pragma unroll
                for (int mt = 0; mt < 2; mt++)
                    #pragma unroll
                    for (int g = 0; g < 4; g++) {
                        mma_bf(acc[mt][2*g],   al[mt], bf4[g][0], bf4[g][1]);
                        mma_bf(acc[mt][2*g+1], al[mt], bf4[g][2], bf4[g][3]);
                    }
                uint32_t bl4[4][4];
                #pragma unroll
                for (int g = 0; g < 4; g++)
                    LDM_X4(bl4[g], stb + 49152 + SWZ(boff[g] + kb));
                #pragma unroll
                for (int mt = 0; mt < 2; mt++)
                    #pragma unroll
                    for (int g = 0; g < 4; g++) {
                        mma_bf(acc[mt][2*g],   ah[mt], bl4[g][0], bl4[g][1]);
                        mma_bf(acc[mt][2*g+1], ah[mt], bl4[g][2], bl4[g][3]);
                    }
            }
        }
        __syncthreads();

        const int cn = c + STAGES;
        if (cn < NC) {
            const char* ga_h = (const char*)Ahi + (at0 + cn) * 16384;
            const char* gb_h = (const char*)Bhi + (bt0 + cn) * 16384;
            const char* ga_l = (TERMS == 3) ? (const char*)Alo + (at0 + cn) * 16384 : nullptr;
            const char* gb_l = (TERMS == 3) ? (const char*)Blo + (bt0 + cn) * 16384 : nullptr;
            const uint32_t ds = sb + (uint32_t)(c % STAGES) * STG_BYTES;
            #pragma unroll
            for (int i = 0; i < 4; i++) {
                const int idx = (tid + (i << 8)) << 4;
                cpasync16(ds +     0 + idx, ga_h + idx);
                cpasync16(ds + 32768 + idx, gb_h + idx);
                if (TERMS == 3) {
                    cpasync16(ds + 16384 + idx, ga_l + idx);
                    cpasync16(ds + 49152 + idx, gb_l + idx);
                }
            }
        }
        CP_COMMIT();   // commit even if empty to keep group accounting aligned
    }

    // ---- epilogue ----
    #pragma unroll
    for (int mt = 0; mt < 2; mt++) {
        const int r0 = bm + wm0 + (mt << 4) + (lane >> 2);
        #pragma unroll
        for (int nt = 0; nt < 8; nt++) {
            const int col = bn + wn0 + (nt << 3) + ((lane & 3) << 1);
            float va0 = acc[mt][nt][0], va1 = acc[mt][nt][1];
            float vb0 = acc[mt][nt][2], vb1 = acc[mt][nt][3];
            if (bias) {
                const float2 bv = *reinterpret_cast<const float2*>(bias + col);
                va0 += bv.x; va1 += bv.y; vb0 += bv.x; vb1 += bv.y;
            }
            if (flags & FLAG_GELU) {
                va0 = gelu_exact(va0); va1 = gelu_exact(va1);
                vb0 = gelu_exact(vb0); vb1 = gelu_exact(vb1);
            }
            if (flags & FLAG_PACK) {
                #pragma unroll
                for (int rr = 0; rr < 2; rr++) {
                    const int r = r0 + (rr << 3);
                    const float pa = rr ? vb0 : va0;
                    const float pb = rr ? vb1 : va1;
                    uint32_t hv, lv;
                    pack2(pa, pb, hv, lv);
                    const size_t tile = (size_t)(r >> 7) * packNC + (col >> 6);
                    const uint32_t off = SWZ((uint32_t)((r & 127) * 128 + ((col & 63) << 1)));
                    *reinterpret_cast<uint32_t*>((char*)Phi + tile * 16384 + off) = hv;
                    if (col < loCols)
                        *reinterpret_cast<uint32_t*>((char*)Plo + tile * 16384 + off) = lv;
                }
            } else {
                float* p0 = C + (size_t)r0 * N + col;
                float* p1 = C + (size_t)(r0 + 8) * N + col;
                if (flags & FLAG_RESID) {
                    const float2 c0 = *reinterpret_cast<const float2*>(p0);
                    const float2 c1 = *reinterpret_cast<const float2*>(p1);
                    va0 += c0.x; va1 += c0.y; vb0 += c1.x; vb1 += c1.y;
                }
                *reinterpret_cast<float2*>(p0) = make_float2(va0, va1);
                *reinterpret_cast<float2*>(p1) = make_float2(vb0, vb1);
            }
        }
    }
}

// ---------------- mma.sync flash attention, single bf16, hd=64 ---------------
// CTA: 128 threads (4 warps), 64 q-rows, kv tiles of 64, double-buffered K/V.
// Input: packed QKV hi tiles (packNC=48). Output: packed hi (packNC=16).
#define ATT_SMEM (8192 + 2 * 16384)   // Q hi + 2 stages * (Kh 8K | Vh 8K)

__global__ __launch_bounds__(128, 3) void attn_mma(
    const __nv_bfloat16* __restrict__ qkvh, __nv_bfloat16* __restrict__ ohi)
{
    extern __shared__ __align__(1024) char asmem[];
    const uint32_t sb = smem_u32(asmem);
    const int tid = threadIdx.x;
    const int wid = tid >> 5, lane = tid & 31;
    const int bh = blockIdx.y;
    const int bb = bh >> 4, h = bh & 15;
    const int q0 = blockIdx.x << 6;
    const int grow0 = bb * SEQ + q0;
    const int hq = h;
    const int hk = (DIMN >> 6) + h;
    const int hv = (2 * DIMN >> 6) + h;

    auto src64 = [&](int coltile, int grows) -> const char* {
        return (const char*)qkvh + ((size_t)(grows >> 7) * 48 + coltile) * 16384
               + (size_t)(grows & 127) * 128;
    };
    auto issue_stage = [&](int it) {
        const int gkv = bb * SEQ + (it << 6);
        const char* kh_ = src64(hk, gkv);
        const char* vh_ = src64(hv, gkv);
        const uint32_t ds = sb + 8192 + (uint32_t)(it & 1) * 16384;
        #pragma unroll
        for (int i = 0; i < 4; i++) {
            const int idx = (tid + (i << 7)) << 4;
            cpasync16(ds +        idx, kh_ + idx);
            cpasync16(ds + 8192 + idx, vh_ + idx);
        }
    };

    // ---- prologue: Q hi + KV stage 0 ----
    {
        const char* qh_ = src64(hq, grow0);
        #pragma unroll
        for (int i = 0; i < 4; i++) {
            const int idx = (tid + (i << 7)) << 4;
            cpasync16(sb + idx, qh_ + idx);
        }
        issue_stage(0);
        CP_COMMIT();
    }
    CP_WAIT(0);
    __syncthreads();

    // ---- preload Q fragments ----
    const uint32_t aoff = (uint32_t)(((wid << 4) + (lane & 15)) * 128 + ((lane >> 4) << 4));
    uint32_t qhf[4][4];
    #pragma unroll
    for (int kb = 0; kb < 4; kb++)
        LDM_X4(qhf[kb], sb + SWZ(aoff + (kb << 5)));

    uint32_t boffK[4], voffV[4];
    #pragma unroll
    for (int g = 0; g < 4; g++) {
        boffK[g] = (uint32_t)(((g << 4) + (lane & 7) + ((lane >> 1) & 8)) * 128 +
                              ((lane & 8) << 1));
        voffV[g] = (uint32_t)((lane & 15) * 128 + ((lane >> 4) << 4) + (g << 5));
    }

    float oacc[8][4];
    #pragma unroll
    for (int j = 0; j < 8; j++)
        #pragma unroll
        for (int u = 0; u < 4; u++) oacc[j][u] = 0.f;
    float m0 = -1e30f, m1 = -1e30f, l0 = 0.f, l1 = 0.f;

    const int NIT = SEQ / 64;
    for (int it = 0; it < NIT; it++) {
        if (it + 1 < NIT) issue_stage(it + 1);
        CP_COMMIT();

        const uint32_t kbuf = sb + 8192 + (uint32_t)(it & 1) * 16384;
        const uint32_t vbuf = kbuf + 8192;

        // ---- S = Q K^T (single bf16) ----
        float sacc[8][4];
        #pragma unroll
        for (int j = 0; j < 8; j++)
            #pragma unroll
            for (int u = 0; u < 4; u++) sacc[j][u] = 0.f;

        #pragma unroll
        for (int kb = 0; kb < 4; kb++) {
            const uint32_t kbb = (uint32_t)(kb << 5);
            uint32_t bh4[4][4];
            #pragma unroll
            for (int g = 0; g < 4; g++)
                LDM_X4(bh4[g], kbuf + SWZ(boffK[g] + kbb));
            #pragma unroll
            for (int g = 0; g < 4; g++) {
                mma_bf(sacc[2*g],   qhf[kb], bh4[g][0], bh4[g][1]);
                mma_bf(sacc[2*g+1], qhf[kb], bh4[g][2], bh4[g][3]);
            }
        }

        // ---- online softmax ----
        #pragma unroll
        for (int j = 0; j < 8; j++)
            #pragma unroll
            for (int u = 0; u < 4; u++) sacc[j][u] *= ASCALE;

        float mx0 = -1e30f, mx1 = -1e30f;
        #pragma unroll
        for (int j = 0; j < 8; j++) {
            mx0 = fmaxf(mx0, fmaxf(sacc[j][0], sacc[j][1]));
            mx1 = fmaxf(mx1, fmaxf(sacc[j][2], sacc[j][3]));
        }
        mx0 = fmaxf(mx0, __shfl_xor_sync(0xffffffffu, mx0, 1));
        mx0 = fmaxf(mx0, __shfl_xor_sync(0xffffffffu, mx0, 2));
        mx1 = fmaxf(mx1, __shfl_xor_sync(0xffffffffu, mx1, 1));
        mx1 = fmaxf(mx1, __shfl_xor_sync(0xffffffffu, mx1, 2));
        const float nm0 = fmaxf(m0, mx0), nm1 = fmaxf(m1, mx1);
        const float al0 = __expf(m0 - nm0), al1 = __expf(m1 - nm1);
        m0 = nm0; m1 = nm1;
        float rs0 = 0.f, rs1 = 0.f;
        #pragma unroll
        for (int j = 0; j < 8; j++) {
            sacc[j][0] = __expf(sacc[j][0] - m0); rs0 += sacc[j][0];
            sacc[j][1] = __expf(sacc[j][1] - m0); rs0 += sacc[j][1];
            sacc[j][2] = __expf(sacc[j][2] - m1); rs1 += sacc[j][2];
            sacc[j][3] = __expf(sacc[j][3] - m1); rs1 += sacc[j][3];
        }
        l0 = l0 * al0 + rs0;
        l1 = l1 * al1 + rs1;
        #pragma unroll
        for (int j = 0; j < 8; j++) {
            oacc[j][0] *= al0; oacc[j][1] *= al0;
            oacc[j][2] *= al1; oacc[j][3] *= al1;
        }

        // ---- O += P V (single bf16 P and V) ----
        #pragma unroll
        for (int jp = 0; jp < 4; jp++) {
            uint32_t pah[4];
            pah[0] = bfpair(sacc[2*jp][0],   sacc[2*jp][1]);
            pah[1] = bfpair(sacc[2*jp][2],   sacc[2*jp][3]);
            pah[2] = bfpair(sacc[2*jp+1][0], sacc[2*jp+1][1]);
            pah[3] = bfpair(sacc[2*jp+1][2], sacc[2*jp+1][3]);
            const uint32_t rowb = (uint32_t)(jp << 11);     // 16 rows * 128B
            #pragma unroll
            for (int g = 0; g < 4; g++) {
                uint32_t vh4[4];
                LDM_X4T(vh4, vbuf + SWZ(voffV[g] + rowb));
                mma_bf(oacc[2*g],   pah, vh4[0], vh4[1]);
                mma_bf(oacc[2*g+1], pah, vh4[2], vh4[3]);
            }
        }

        if (it + 1 < NIT) CP_WAIT(0);
        __syncthreads();
    }

    // ---- finalize & write hi ----
    l0 += __shfl_xor_sync(0xffffffffu, l0, 1);
    l0 += __shfl_xor_sync(0xffffffffu, l0, 2);
    l1 += __shfl_xor_sync(0xffffffffu, l1, 1);
    l1 += __shfl_xor_sync(0xffffffffu, l1, 2);
    const float il0 = 1.0f / l0, il1 = 1.0f / l1;

    const int r0g = grow0 + (wid << 4) + (lane >> 2);
    #pragma unroll
    for (int j = 0; j < 8; j++) {
        const int k0 = h * HD + (j << 3) + ((lane & 3) << 1);
        const uint32_t hv0 = bfpair(oacc[j][0] * il0, oacc[j][1] * il0);
        const uint32_t hv1 = bfpair(oacc[j][2] * il1, oacc[j][3] * il1);
        const size_t t0 = (size_t)(r0g >> 7) * 16 + (k0 >> 6);
        const uint32_t of0 = SWZ((uint32_t)((r0g & 127) * 128 + ((k0 & 63) << 1)));
        *reinterpret_cast<uint32_t*>((char*)ohi + t0 * 16384 + of0) = hv0;
        const int r1g = r0g + 8;
        const size_t t1 = (size_t)(r1g >> 7) * 16 + (k0 >> 6);
        const uint32_t of1 = SWZ((uint32_t)((r1g & 127) * 128 + ((k0 & 63) << 1)));
        *reinterpret_cast<uint32_t*>((char*)ohi + t1 * 16384 + of1) = hv1;
    }
}

// ---------------- launch ----------------
extern "C" void kernel_launch(void* const* d_in, const int* in_sizes, int n_in,
                              void* d_out, int out_size)
{
    const float* x    = (const float*)d_in[0];
    const float* Wqkv = (const float*)d_in[1];
    const float* Wout = (const float*)d_in[2];
    const float* bout = (const float*)d_in[3];
    const float* ln1g = (const float*)d_in[4];
    const float* ln1b = (const float*)d_in[5];
    const float* ln2g = (const float*)d_in[6];
    const float* ln2b = (const float*)d_in[7];
    const float* W1   = (const float*)d_in[8];
    const float* b1   = (const float*)d_in[9];
    const float* W2   = (const float*)d_in[10];
    const float* b2   = (const float*)d_in[11];
    float* h = (float*)d_out;

    __nv_bfloat16 *yh, *yl, *qph, *ath, *uh, *ul;
    cudaGetSymbolAddress((void**)&yh,  g_y_hi);
    cudaGetSymbolAddress((void**)&yl,  g_y_lo);
    cudaGetSymbolAddress((void**)&qph, g_qp_hi);
    cudaGetSymbolAddress((void**)&ath, g_at_hi);
    cudaGetSymbolAddress((void**)&uh,  g_u_hi);
    cudaGetSymbolAddress((void**)&ul,  g_u_lo);
    __nv_bfloat16 *wqh, *woh, *w1h, *w1l, *w2h, *w2l;
    cudaGetSymbolAddress((void**)&wqh, g_wq_hi);
    cudaGetSymbolAddress((void**)&woh, g_wo_hi);
    cudaGetSymbolAddress((void**)&w1h, g_w1_hi);
    cudaGetSymbolAddress((void**)&w1l, g_w1_lo);
    cudaGetSymbolAddress((void**)&w2h, g_w2_hi);
    cudaGetSymbolAddress((void**)&w2l, g_w2_lo);

    cudaFuncSetAttribute(gemm_mma<1>, cudaFuncAttributeMaxDynamicSharedMemorySize, GEMM_SMEM);
    cudaFuncSetAttribute(gemm_mma<3>, cudaFuncAttributeMaxDynamicSharedMemorySize, GEMM_SMEM);
    cudaFuncSetAttribute(attn_mma, cudaFuncAttributeMaxDynamicSharedMemorySize, ATT_SMEM);

    // pack weights: hi-only for Wqkv/Wout, hi+lo for W1/W2
    prep_kernel<<<dim3(3 * DIMN / 128, DIMN / 64, DEPTH), 256>>>(Wqkv, wqh, nullptr, DIMN, 3 * DIMN);
    prep_kernel<<<dim3(DIMN / 128,     DIMN / 64, DEPTH), 256>>>(Wout, woh, nullptr, DIMN, DIMN);
    prep_kernel<<<dim3(MLPD / 128,     DIMN / 64, DEPTH), 256>>>(W1,   w1h, w1l, DIMN, MLPD);
    prep_kernel<<<dim3(DIMN / 128,     MLPD / 64, DEPTH), 256>>>(W2,   w2h, w2l, MLPD, DIMN);

    cudaMemcpyAsync(h, x, (size_t)TOK * DIMN * sizeof(float), cudaMemcpyDeviceToDevice);

    for (int l = 0; l < DEPTH; l++) {
        const size_t woffQ = (size_t)l * DIMN * 3 * DIMN;
        const size_t woffO = (size_t)l * DIMN * DIMN;
        const size_t woff1 = (size_t)l * DIMN * MLPD;
        const size_t woff2 = (size_t)l * MLPD * DIMN;
        const float* bo  = bout + (size_t)l * DIMN;
        const float* g1  = ln1g + (size_t)l * DIMN;
        const float* bb1 = ln1b + (size_t)l * DIMN;
        const float* g2  = ln2g + (size_t)l * DIMN;
        const float* bb2 = ln2b + (size_t)l * DIMN;
        const float* bf1 = b1   + (size_t)l * MLPD;
        const float* bf2 = b2   + (size_t)l * DIMN;

        ln_pack<<<TOK, 256>>>(h, g1, bb1, yh, yl);
        gemm_mma<1><<<dim3(3 * DIMN / 128, TOK / 128), 256, GEMM_SMEM>>>(
            TOK, 3 * DIMN, DIMN, yh, nullptr, wqh + woffQ, nullptr,
            nullptr, nullptr, qph, nullptr, 3 * DIMN / 64, 0, FLAG_PACK);
        attn_mma<<<dim3(SEQ / 64, BATCH * HEADS), 128, ATT_SMEM>>>(qph, ath);
        gemm_mma<1><<<dim3(DIMN / 128, TOK / 128), 256, GEMM_SMEM>>>(
            TOK, DIMN, DIMN, ath, nullptr, woh + woffO, nullptr,
            h, bo, nullptr, nullptr, 0, 0, FLAG_RESID);
        ln_pack<<<TOK, 256>>>(h, g2, bb2, yh, yl);
        gemm_mma<3><<<dim3(MLPD / 128, TOK / 128), 256, GEMM_SMEM>>>(
            TOK, MLPD, DIMN, yh, yl, w1h + woff1, w1l + woff1,
            nullptr, bf1, uh, ul, MLPD / 64, MLPD, FLAG_GELU | FLAG_PACK);
        gemm_mma<3><<<dim3(DIMN / 128, TOK / 128), 256, GEMM_SMEM>>>(
            TOK, DIMN, MLPD, uh, ul, w2h + woff2, w2l + woff2,
            h, bf2, nullptr, nullptr, 0, 0, FLAG_RESID);
    }
}